// round 1
// baseline (speedup 1.0000x reference)
#include <cuda_runtime.h>

#define HH 1024
#define WW 1024
#define NIMG 12            // 4 * 3
#define RAD 40
#define PLANE (HH * WW)
#define NTOT (NIMG * PLANE)
#define EPSV 1e-3f
#define VSEG 128           // rows per vertical-pass block segment

// Scratch (device globals — no runtime allocation allowed).
// g_s1: stage-1 horizontal box sums of {I, P, I*P, I*I}; reused (slots 0,1) for
//       stage-3 horizontal box sums of {a, b}.
// g_ab: pointwise a, b.
__device__ float g_s1[4][NTOT];
__device__ float g_ab[2][NTOT];

__device__ __forceinline__ float warp_incl_scan(float v, int lane) {
#pragma unroll
    for (int o = 1; o < 32; o <<= 1) {
        float n = __shfl_up_sync(0xFFFFFFFFu, v, o);
        if (lane >= o) v += n;
    }
    return v;
}

// ---------------------------------------------------------------------------
// Stage 1: horizontal box sum of 4 derived channels via block prefix scan.
// One block per (image,row). 256 threads x 4 elements = 1024 columns.
// ---------------------------------------------------------------------------
__global__ void __launch_bounds__(256) hscan4_kernel(const float* __restrict__ I,
                                                     const float* __restrict__ P) {
    const int row = blockIdx.x;                 // 0 .. NIMG*HH-1
    const size_t base = (size_t)row * WW;
    const int tid = threadIdx.x;
    const int lane = tid & 31, wid = tid >> 5;
    const int i0 = tid * 4;

    __shared__ float csp[WW + 1];
    __shared__ float wsum[8];

    const float4 av = ((const float4*)(I + base))[tid];
    const float4 bv = ((const float4*)(P + base))[tid];
    if (tid == 0) csp[0] = 0.0f;

#pragma unroll
    for (int c = 0; c < 4; ++c) {
        float v0, v1, v2, v3;
        if (c == 0)      { v0 = av.x;        v1 = av.y;        v2 = av.z;        v3 = av.w; }
        else if (c == 1) { v0 = bv.x;        v1 = bv.y;        v2 = bv.z;        v3 = bv.w; }
        else if (c == 2) { v0 = av.x * bv.x; v1 = av.y * bv.y; v2 = av.z * bv.z; v3 = av.w * bv.w; }
        else             { v0 = av.x * av.x; v1 = av.y * av.y; v2 = av.z * av.z; v3 = av.w * av.w; }

        const float l0 = v0, l1 = l0 + v1, l2 = l1 + v2, l3 = l2 + v3;
        const float ws = warp_incl_scan(l3, lane);
        if (lane == 31) wsum[wid] = ws;
        __syncthreads();
        if (tid == 0) {
            float acc = 0.0f;
#pragma unroll
            for (int w = 0; w < 8; ++w) { float t = wsum[w]; wsum[w] = acc; acc += t; }
        }
        __syncthreads();
        const float off = wsum[wid] + ws - l3;
        csp[i0 + 1] = off + l0;
        csp[i0 + 2] = off + l1;
        csp[i0 + 3] = off + l2;
        csp[i0 + 4] = off + l3;
        __syncthreads();

        float4 o;
        o.x = csp[min(i0 + 0 + RAD + 1, WW)] - csp[max(i0 + 0 - RAD, 0)];
        o.y = csp[min(i0 + 1 + RAD + 1, WW)] - csp[max(i0 + 1 - RAD, 0)];
        o.z = csp[min(i0 + 2 + RAD + 1, WW)] - csp[max(i0 + 2 - RAD, 0)];
        o.w = csp[min(i0 + 3 + RAD + 1, WW)] - csp[max(i0 + 3 - RAD, 0)];
        ((float4*)(g_s1[c] + base))[tid] = o;
        __syncthreads();
    }
}

// ---------------------------------------------------------------------------
// Stage 3: horizontal box sum of {a, b}.
// ---------------------------------------------------------------------------
__global__ void __launch_bounds__(256) hscan2_kernel() {
    const int row = blockIdx.x;
    const size_t base = (size_t)row * WW;
    const int tid = threadIdx.x;
    const int lane = tid & 31, wid = tid >> 5;
    const int i0 = tid * 4;

    __shared__ float csp[WW + 1];
    __shared__ float wsum[8];

    if (tid == 0) csp[0] = 0.0f;

#pragma unroll
    for (int c = 0; c < 2; ++c) {
        const float4 v = ((const float4*)(g_ab[c] + base))[tid];
        const float l0 = v.x, l1 = l0 + v.y, l2 = l1 + v.z, l3 = l2 + v.w;
        const float ws = warp_incl_scan(l3, lane);
        if (lane == 31) wsum[wid] = ws;
        __syncthreads();
        if (tid == 0) {
            float acc = 0.0f;
#pragma unroll
            for (int w = 0; w < 8; ++w) { float t = wsum[w]; wsum[w] = acc; acc += t; }
        }
        __syncthreads();
        const float off = wsum[wid] + ws - l3;
        csp[i0 + 1] = off + l0;
        csp[i0 + 2] = off + l1;
        csp[i0 + 3] = off + l2;
        csp[i0 + 4] = off + l3;
        __syncthreads();

        float4 o;
        o.x = csp[min(i0 + 0 + RAD + 1, WW)] - csp[max(i0 + 0 - RAD, 0)];
        o.y = csp[min(i0 + 1 + RAD + 1, WW)] - csp[max(i0 + 1 - RAD, 0)];
        o.z = csp[min(i0 + 2 + RAD + 1, WW)] - csp[max(i0 + 2 - RAD, 0)];
        o.w = csp[min(i0 + 3 + RAD + 1, WW)] - csp[max(i0 + 3 - RAD, 0)];
        ((float4*)(g_s1[c] + base))[tid] = o;
        __syncthreads();
    }
}

// ---------------------------------------------------------------------------
// Stage 2: vertical sliding-window box sum of 4 channels + fused a,b compute.
// Block = 256 columns; covers VSEG output rows with +/-RAD halo reads.
// ---------------------------------------------------------------------------
__global__ void __launch_bounds__(256) vab_kernel() {
    const int img = blockIdx.z;
    const int col = blockIdx.x * 256 + threadIdx.x;
    const int r0  = blockIdx.y * VSEG;
    const size_t pb = (size_t)img * PLANE + col;

    const float* __restrict__ p0 = g_s1[0] + pb;
    const float* __restrict__ p1 = g_s1[1] + pb;
    const float* __restrict__ p2 = g_s1[2] + pb;
    const float* __restrict__ p3 = g_s1[3] + pb;

    float s0 = 0.f, s1 = 0.f, s2 = 0.f, s3 = 0.f;
    const int lo = max(r0 - RAD, 0);
    const int hi = min(r0 + RAD, HH - 1);
    for (int rw = lo; rw <= hi; ++rw) {
        const size_t o = (size_t)rw * WW;
        s0 += p0[o]; s1 += p1[o]; s2 += p2[o]; s3 += p3[o];
    }

    const float cx = (float)(min(col + RAD, WW - 1) - max(col - RAD, 0) + 1);

#pragma unroll 4
    for (int rr = r0; rr < r0 + VSEG; ++rr) {
        const float cy  = (float)(min(rr + RAD, HH - 1) - max(rr - RAD, 0) + 1);
        const float inv = 1.0f / (cx * cy);
        const float mI  = s0 * inv;
        const float mP  = s1 * inv;
        const float mIP = s2 * inv;
        const float mII = s3 * inv;
        const float varI = mII - mI * mI;
        const float a = (mIP - mI * mP) / (varI + EPSV);
        const float b = mP - a * mI;
        const size_t o = (size_t)rr * WW;
        g_ab[0][pb + o] = a;
        g_ab[1][pb + o] = b;

        const int ar = rr + RAD + 1;
        if (ar < HH) {
            const size_t oa = (size_t)ar * WW;
            s0 += p0[oa]; s1 += p1[oa]; s2 += p2[oa]; s3 += p3[oa];
        }
        const int sr = rr - RAD;
        if (sr >= 0) {
            const size_t os = (size_t)sr * WW;
            s0 -= p0[os]; s1 -= p1[os]; s2 -= p2[os]; s3 -= p3[os];
        }
    }
}

// ---------------------------------------------------------------------------
// Stage 4: vertical box sum of {a,b} + fused output  out = mean_a * I + mean_b
// ---------------------------------------------------------------------------
__global__ void __launch_bounds__(256) vout_kernel(const float* __restrict__ I,
                                                   float* __restrict__ out) {
    const int img = blockIdx.z;
    const int col = blockIdx.x * 256 + threadIdx.x;
    const int r0  = blockIdx.y * VSEG;
    const size_t pb = (size_t)img * PLANE + col;

    const float* __restrict__ pa = g_s1[0] + pb;
    const float* __restrict__ pbp = g_s1[1] + pb;

    float sa = 0.f, sb = 0.f;
    const int lo = max(r0 - RAD, 0);
    const int hi = min(r0 + RAD, HH - 1);
    for (int rw = lo; rw <= hi; ++rw) {
        const size_t o = (size_t)rw * WW;
        sa += pa[o]; sb += pbp[o];
    }

    const float cx = (float)(min(col + RAD, WW - 1) - max(col - RAD, 0) + 1);

#pragma unroll 4
    for (int rr = r0; rr < r0 + VSEG; ++rr) {
        const float cy  = (float)(min(rr + RAD, HH - 1) - max(rr - RAD, 0) + 1);
        const float inv = 1.0f / (cx * cy);
        const float ma = sa * inv;
        const float mb = sb * inv;
        const size_t o = (size_t)rr * WW;
        out[pb + o] = ma * I[pb + o] + mb;

        const int ar = rr + RAD + 1;
        if (ar < HH) {
            const size_t oa = (size_t)ar * WW;
            sa += pa[oa]; sb += pbp[oa];
        }
        const int sr = rr - RAD;
        if (sr >= 0) {
            const size_t os = (size_t)sr * WW;
            sa -= pa[os]; sb -= pbp[os];
        }
    }
}

extern "C" void kernel_launch(void* const* d_in, const int* in_sizes, int n_in,
                              void* d_out, int out_size) {
    const float* I = (const float*)d_in[0];
    const float* P = (const float*)d_in[1];
    float* out = (float*)d_out;

    hscan4_kernel<<<NIMG * HH, 256>>>(I, P);
    vab_kernel<<<dim3(WW / 256, HH / VSEG, NIMG), 256>>>();
    hscan2_kernel<<<NIMG * HH, 256>>>();
    vout_kernel<<<dim3(WW / 256, HH / VSEG, NIMG), 256>>>(I, out);
}

// round 2
// speedup vs baseline: 1.8084x; 1.8084x over previous
#include <cuda_runtime.h>

#define HH 1024
#define WW 1024
#define NIMG 12            // 4 * 3
#define RAD 40
#define PLANE (HH * WW)
#define NTOT (NIMG * PLANE)
#define EPSV 1e-3f
#define VSEG 64            // rows per vertical-pass block segment

// Scratch (device globals — no runtime allocation allowed).
__device__ float g_s1[4][NTOT];
__device__ float g_ab[2][NTOT];

__device__ __forceinline__ float warp_incl_scan(float v, int lane) {
#pragma unroll
    for (int o = 1; o < 32; o <<= 1) {
        float n = __shfl_up_sync(0xFFFFFFFFu, v, o);
        if (lane >= o) v += n;
    }
    return v;
}

// ---------------------------------------------------------------------------
// Stage 1: horizontal box sum of 4 derived channels via block prefix scan.
// ---------------------------------------------------------------------------
__global__ void __launch_bounds__(256) hscan4_kernel(const float* __restrict__ I,
                                                     const float* __restrict__ P) {
    const int row = blockIdx.x;
    const size_t base = (size_t)row * WW;
    const int tid = threadIdx.x;
    const int lane = tid & 31, wid = tid >> 5;
    const int i0 = tid * 4;

    __shared__ float csp[WW + 1];
    __shared__ float wsum[8];

    const float4 av = ((const float4*)(I + base))[tid];
    const float4 bv = ((const float4*)(P + base))[tid];
    if (tid == 0) csp[0] = 0.0f;

#pragma unroll
    for (int c = 0; c < 4; ++c) {
        float v0, v1, v2, v3;
        if (c == 0)      { v0 = av.x;        v1 = av.y;        v2 = av.z;        v3 = av.w; }
        else if (c == 1) { v0 = bv.x;        v1 = bv.y;        v2 = bv.z;        v3 = bv.w; }
        else if (c == 2) { v0 = av.x * bv.x; v1 = av.y * bv.y; v2 = av.z * bv.z; v3 = av.w * bv.w; }
        else             { v0 = av.x * av.x; v1 = av.y * av.y; v2 = av.z * av.z; v3 = av.w * av.w; }

        const float l0 = v0, l1 = l0 + v1, l2 = l1 + v2, l3 = l2 + v3;
        const float ws = warp_incl_scan(l3, lane);
        if (lane == 31) wsum[wid] = ws;
        __syncthreads();
        if (tid == 0) {
            float acc = 0.0f;
#pragma unroll
            for (int w = 0; w < 8; ++w) { float t = wsum[w]; wsum[w] = acc; acc += t; }
        }
        __syncthreads();
        const float off = wsum[wid] + ws - l3;
        csp[i0 + 1] = off + l0;
        csp[i0 + 2] = off + l1;
        csp[i0 + 3] = off + l2;
        csp[i0 + 4] = off + l3;
        __syncthreads();

        float4 o;
        o.x = csp[min(i0 + 0 + RAD + 1, WW)] - csp[max(i0 + 0 - RAD, 0)];
        o.y = csp[min(i0 + 1 + RAD + 1, WW)] - csp[max(i0 + 1 - RAD, 0)];
        o.z = csp[min(i0 + 2 + RAD + 1, WW)] - csp[max(i0 + 2 - RAD, 0)];
        o.w = csp[min(i0 + 3 + RAD + 1, WW)] - csp[max(i0 + 3 - RAD, 0)];
        ((float4*)(g_s1[c] + base))[tid] = o;
        __syncthreads();
    }
}

// ---------------------------------------------------------------------------
// Stage 3: horizontal box sum of {a, b}.
// ---------------------------------------------------------------------------
__global__ void __launch_bounds__(256) hscan2_kernel() {
    const int row = blockIdx.x;
    const size_t base = (size_t)row * WW;
    const int tid = threadIdx.x;
    const int lane = tid & 31, wid = tid >> 5;
    const int i0 = tid * 4;

    __shared__ float csp[WW + 1];
    __shared__ float wsum[8];

    if (tid == 0) csp[0] = 0.0f;

#pragma unroll
    for (int c = 0; c < 2; ++c) {
        const float4 v = ((const float4*)(g_ab[c] + base))[tid];
        const float l0 = v.x, l1 = l0 + v.y, l2 = l1 + v.z, l3 = l2 + v.w;
        const float ws = warp_incl_scan(l3, lane);
        if (lane == 31) wsum[wid] = ws;
        __syncthreads();
        if (tid == 0) {
            float acc = 0.0f;
#pragma unroll
            for (int w = 0; w < 8; ++w) { float t = wsum[w]; wsum[w] = acc; acc += t; }
        }
        __syncthreads();
        const float off = wsum[wid] + ws - l3;
        csp[i0 + 1] = off + l0;
        csp[i0 + 2] = off + l1;
        csp[i0 + 3] = off + l2;
        csp[i0 + 4] = off + l3;
        __syncthreads();

        float4 o;
        o.x = csp[min(i0 + 0 + RAD + 1, WW)] - csp[max(i0 + 0 - RAD, 0)];
        o.y = csp[min(i0 + 1 + RAD + 1, WW)] - csp[max(i0 + 1 - RAD, 0)];
        o.z = csp[min(i0 + 2 + RAD + 1, WW)] - csp[max(i0 + 2 - RAD, 0)];
        o.w = csp[min(i0 + 3 + RAD + 1, WW)] - csp[max(i0 + 3 - RAD, 0)];
        ((float4*)(g_s1[c] + base))[tid] = o;
        __syncthreads();
    }
}

// ---------------------------------------------------------------------------
// Stage 2: vertical sliding-window box sum of 4 channels + fused a,b compute.
// Batched loads (4 rows/batch x 4ch x add+sub = 32 LDGs in flight).
// ---------------------------------------------------------------------------
__global__ void __launch_bounds__(256) vab_kernel() {
    const int img = blockIdx.z;
    const int col = blockIdx.x * 256 + threadIdx.x;
    const int r0  = blockIdx.y * VSEG;
    const size_t pb = (size_t)img * PLANE + col;

    const float* __restrict__ p0 = g_s1[0] + pb;
    const float* __restrict__ p1 = g_s1[1] + pb;
    const float* __restrict__ p2 = g_s1[2] + pb;
    const float* __restrict__ p3 = g_s1[3] + pb;

    float s0 = 0.f, s1 = 0.f, s2 = 0.f, s3 = 0.f;
    const int lo = max(r0 - RAD, 0);
    const int hi = min(r0 + RAD, HH - 1);
#pragma unroll 4
    for (int rw = lo; rw <= hi; ++rw) {
        const size_t o = (size_t)rw * WW;
        s0 += __ldg(p0 + o); s1 += __ldg(p1 + o);
        s2 += __ldg(p2 + o); s3 += __ldg(p3 + o);
    }

    const float cx = (float)(min(col + RAD, WW - 1) - max(col - RAD, 0) + 1);

    for (int base = 0; base < VSEG; base += 4) {
        float a0[4], a1[4], a2[4], a3[4];
        float d0[4], d1[4], d2[4], d3[4];
#pragma unroll
        for (int k = 0; k < 4; ++k) {
            const int rr = r0 + base + k;
            const int ar = rr + RAD + 1;
            const int sr = rr - RAD;
            const size_t oa = (size_t)min(ar, HH - 1) * WW;
            const size_t os = (size_t)max(sr, 0) * WW;
            const float ma = (ar < HH) ? 1.f : 0.f;
            const float ms = (sr >= 0) ? 1.f : 0.f;
            a0[k] = ma * __ldg(p0 + oa); d0[k] = ms * __ldg(p0 + os);
            a1[k] = ma * __ldg(p1 + oa); d1[k] = ms * __ldg(p1 + os);
            a2[k] = ma * __ldg(p2 + oa); d2[k] = ms * __ldg(p2 + os);
            a3[k] = ma * __ldg(p3 + oa); d3[k] = ms * __ldg(p3 + os);
        }
#pragma unroll
        for (int k = 0; k < 4; ++k) {
            const int rr = r0 + base + k;
            const float cy  = (float)(min(rr + RAD, HH - 1) - max(rr - RAD, 0) + 1);
            const float inv = 1.0f / (cx * cy);
            const float mI  = s0 * inv;
            const float mP  = s1 * inv;
            const float mIP = s2 * inv;
            const float mII = s3 * inv;
            const float varI = mII - mI * mI;
            const float a = (mIP - mI * mP) / (varI + EPSV);
            const float b = mP - a * mI;
            const size_t o = (size_t)rr * WW;
            g_ab[0][pb + o] = a;
            g_ab[1][pb + o] = b;
            s0 += a0[k] - d0[k];
            s1 += a1[k] - d1[k];
            s2 += a2[k] - d2[k];
            s3 += a3[k] - d3[k];
        }
    }
}

// ---------------------------------------------------------------------------
// Stage 4: vertical box sum of {a,b} + fused output  out = mean_a * I + mean_b
// Batched loads (8 rows/batch x 2ch x add+sub = 32 LDGs in flight).
// ---------------------------------------------------------------------------
__global__ void __launch_bounds__(256) vout_kernel(const float* __restrict__ I,
                                                   float* __restrict__ out) {
    const int img = blockIdx.z;
    const int col = blockIdx.x * 256 + threadIdx.x;
    const int r0  = blockIdx.y * VSEG;
    const size_t pb = (size_t)img * PLANE + col;

    const float* __restrict__ pa = g_s1[0] + pb;
    const float* __restrict__ pbp = g_s1[1] + pb;

    float sa = 0.f, sb = 0.f;
    const int lo = max(r0 - RAD, 0);
    const int hi = min(r0 + RAD, HH - 1);
#pragma unroll 4
    for (int rw = lo; rw <= hi; ++rw) {
        const size_t o = (size_t)rw * WW;
        sa += __ldg(pa + o); sb += __ldg(pbp + o);
    }

    const float cx = (float)(min(col + RAD, WW - 1) - max(col - RAD, 0) + 1);

    for (int base = 0; base < VSEG; base += 8) {
        float aa[8], ab[8], da[8], db[8], iv[8];
#pragma unroll
        for (int k = 0; k < 8; ++k) {
            const int rr = r0 + base + k;
            const int ar = rr + RAD + 1;
            const int sr = rr - RAD;
            const size_t oa = (size_t)min(ar, HH - 1) * WW;
            const size_t os = (size_t)max(sr, 0) * WW;
            const float ma = (ar < HH) ? 1.f : 0.f;
            const float ms = (sr >= 0) ? 1.f : 0.f;
            aa[k] = ma * __ldg(pa + oa);  da[k] = ms * __ldg(pa + os);
            ab[k] = ma * __ldg(pbp + oa); db[k] = ms * __ldg(pbp + os);
            iv[k] = __ldg(I + pb + (size_t)rr * WW);
        }
#pragma unroll
        for (int k = 0; k < 8; ++k) {
            const int rr = r0 + base + k;
            const float cy  = (float)(min(rr + RAD, HH - 1) - max(rr - RAD, 0) + 1);
            const float inv = 1.0f / (cx * cy);
            out[pb + (size_t)rr * WW] = (sa * inv) * iv[k] + (sb * inv);
            sa += aa[k] - da[k];
            sb += ab[k] - db[k];
        }
    }
}

extern "C" void kernel_launch(void* const* d_in, const int* in_sizes, int n_in,
                              void* d_out, int out_size) {
    const float* I = (const float*)d_in[0];
    const float* P = (const float*)d_in[1];
    float* out = (float*)d_out;

    hscan4_kernel<<<NIMG * HH, 256>>>(I, P);
    vab_kernel<<<dim3(WW / 256, HH / VSEG, NIMG), 256>>>();
    hscan2_kernel<<<NIMG * HH, 256>>>();
    vout_kernel<<<dim3(WW / 256, HH / VSEG, NIMG), 256>>>(I, out);
}

// round 5
// speedup vs baseline: 2.3752x; 1.3134x over previous
#include <cuda_runtime.h>

#define HH 1024
#define WW 1024
#define NIMG 12
#define RAD 40
#define PLANE (HH * WW)
#define NTOT (NIMG * PLANE)
#define EPSV 1e-3f

#define STRIP 256        // scan strip width (== blockDim.x)
#define OUTW  176        // output columns per block (STRIP - 2*RAD)
#define VSEG  128        // output rows per block
#define NBX   6          // ceil(1024 / 176)

// Scratch: pointwise a, b (only intermediate that touches DRAM).
__device__ float g_ab[2][NTOT];

// ---------------------------------------------------------------------------
// K1: vertical sliding-window sums of {I, P, I*P, I*I} (streamed from GMEM),
//     then per-row horizontal box sum via block scan, then a,b pointwise.
// ---------------------------------------------------------------------------
__global__ void __launch_bounds__(256) gf_k1(const float* __restrict__ I,
                                             const float* __restrict__ P) {
    const int img = blockIdx.z;
    const int tid = threadIdx.x;
    const int lane = tid & 31, wid = tid >> 5;
    const int c  = blockIdx.x * OUTW - RAD + tid;   // global col of this lane
    const int r0 = blockIdx.y * VSEG;
    const float cm = (c >= 0 && c < WW) ? 1.0f : 0.0f;
    const int cc = min(max(c, 0), WW - 1);
    const float* Ip = I + (size_t)img * PLANE + cc;
    const float* Pp = P + (size_t)img * PLANE + cc;

    __shared__ float4 psum[2][STRIP + 1];
    __shared__ float4 wsum[8];

    // --- init vertical window rows [r0-RAD, r0+RAD] ---
    float4 s = make_float4(0.f, 0.f, 0.f, 0.f);
#pragma unroll 4
    for (int k = 0; k < 2 * RAD + 1; ++k) {
        const int rw = r0 - RAD + k;
        const float rm = (rw >= 0 && rw < HH) ? cm : 0.0f;
        const size_t o = (size_t)min(max(rw, 0), HH - 1) * WW;
        const float iv = rm * __ldg(Ip + o);
        const float pv = rm * __ldg(Pp + o);
        s.x += iv; s.y += pv; s.z += iv * pv; s.w += iv * iv;
    }

    const float cx = (float)(min(c + RAD, WW - 1) - max(c - RAD, 0) + 1);
    const bool is_out = (tid >= RAD) && (tid < RAD + OUTW) && (c < WW);

    int buf = 0;
    for (int rr = r0; rr < r0 + VSEG; ++rr) {
        // prefetch streaming updates (hidden behind the scan)
        const int ar = rr + RAD + 1, sr = rr - RAD;
        const float am = (ar < HH) ? cm : 0.0f;
        const float sm = (sr >= 0) ? cm : 0.0f;
        const size_t oa = (size_t)min(ar, HH - 1) * WW;
        const size_t os = (size_t)max(sr, 0) * WW;
        const float ai = am * __ldg(Ip + oa), ap = am * __ldg(Pp + oa);
        const float si = sm * __ldg(Ip + os), sp = sm * __ldg(Pp + os);

        // --- block-wide inclusive scan of s (4 channels) ---
        float4 v = s;
#pragma unroll
        for (int o = 1; o < 32; o <<= 1) {
            float nx = __shfl_up_sync(0xFFFFFFFFu, v.x, o);
            float ny = __shfl_up_sync(0xFFFFFFFFu, v.y, o);
            float nz = __shfl_up_sync(0xFFFFFFFFu, v.z, o);
            float nw = __shfl_up_sync(0xFFFFFFFFu, v.w, o);
            if (lane >= o) { v.x += nx; v.y += ny; v.z += nz; v.w += nw; }
        }
        if (lane == 31) wsum[wid] = v;
        __syncthreads();
        if (tid < 8) {
            float4 w = wsum[tid];
#pragma unroll
            for (int o = 1; o < 8; o <<= 1) {
                float nx = __shfl_up_sync(0xFFu, w.x, o);
                float ny = __shfl_up_sync(0xFFu, w.y, o);
                float nz = __shfl_up_sync(0xFFu, w.z, o);
                float nw = __shfl_up_sync(0xFFu, w.w, o);
                if (tid >= o) { w.x += nx; w.y += ny; w.z += nz; w.w += nw; }
            }
            wsum[tid] = w;   // inclusive warp sums
        }
        __syncthreads();
        float4 off = (wid > 0) ? wsum[wid - 1] : make_float4(0.f, 0.f, 0.f, 0.f);
        float4 C = make_float4(off.x + v.x, off.y + v.y, off.z + v.z, off.w + v.w);
        psum[buf][tid + 1] = C;
        if (tid == 0) psum[buf][0] = make_float4(0.f, 0.f, 0.f, 0.f);
        __syncthreads();

        if (is_out) {
            const float4 h4 = psum[buf][tid + RAD + 1];
            const float4 l4 = psum[buf][tid - RAD];
            const float cy  = (float)(min(rr + RAD, HH - 1) - max(rr - RAD, 0) + 1);
            const float inv = 1.0f / (cx * cy);
            const float mI  = (h4.x - l4.x) * inv;
            const float mP  = (h4.y - l4.y) * inv;
            const float mIP = (h4.z - l4.z) * inv;
            const float mII = (h4.w - l4.w) * inv;
            const float varI = mII - mI * mI;
            const float a = (mIP - mI * mP) / (varI + EPSV);
            const float b = mP - a * mI;
            const size_t o = (size_t)img * PLANE + (size_t)rr * WW + c;
            g_ab[0][o] = a;
            g_ab[1][o] = b;
        }

        // update window
        s.x += ai - si;
        s.y += ap - sp;
        s.z += ai * ap - si * sp;
        s.w += ai * ai - si * si;
        buf ^= 1;
    }
}

// ---------------------------------------------------------------------------
// K2: vertical sliding sums of {a, b}, horizontal box via block scan,
//     fused output: out = mean_a * I + mean_b.
// ---------------------------------------------------------------------------
__global__ void __launch_bounds__(256) gf_k2(const float* __restrict__ I,
                                             float* __restrict__ out) {
    const int img = blockIdx.z;
    const int tid = threadIdx.x;
    const int lane = tid & 31, wid = tid >> 5;
    const int c  = blockIdx.x * OUTW - RAD + tid;
    const int r0 = blockIdx.y * VSEG;
    const float cm = (c >= 0 && c < WW) ? 1.0f : 0.0f;
    const int cc = min(max(c, 0), WW - 1);
    const size_t pb = (size_t)img * PLANE + cc;
    const float* pa = g_ab[0] + pb;
    const float* pbv = g_ab[1] + pb;

    __shared__ float2 psum[2][STRIP + 1];
    __shared__ float2 wsum[8];

    float2 s = make_float2(0.f, 0.f);
#pragma unroll 4
    for (int k = 0; k < 2 * RAD + 1; ++k) {
        const int rw = r0 - RAD + k;
        const float rm = (rw >= 0 && rw < HH) ? cm : 0.0f;
        const size_t o = (size_t)min(max(rw, 0), HH - 1) * WW;
        s.x += rm * __ldg(pa + o);
        s.y += rm * __ldg(pbv + o);
    }

    const float cx = (float)(min(c + RAD, WW - 1) - max(c - RAD, 0) + 1);
    const bool is_out = (tid >= RAD) && (tid < RAD + OUTW) && (c < WW);

    int buf = 0;
    for (int rr = r0; rr < r0 + VSEG; ++rr) {
        const int ar = rr + RAD + 1, sr = rr - RAD;
        const float am = (ar < HH) ? cm : 0.0f;
        const float sm = (sr >= 0) ? cm : 0.0f;
        const size_t oa = (size_t)min(ar, HH - 1) * WW;
        const size_t os = (size_t)max(sr, 0) * WW;
        const float aa = am * __ldg(pa + oa), ab = am * __ldg(pbv + oa);
        const float sa = sm * __ldg(pa + os), sb = sm * __ldg(pbv + os);
        const float iv = is_out ? __ldg(I + (size_t)img * PLANE + (size_t)rr * WW + c) : 0.0f;

        float2 v = s;
#pragma unroll
        for (int o = 1; o < 32; o <<= 1) {
            float nx = __shfl_up_sync(0xFFFFFFFFu, v.x, o);
            float ny = __shfl_up_sync(0xFFFFFFFFu, v.y, o);
            if (lane >= o) { v.x += nx; v.y += ny; }
        }
        if (lane == 31) wsum[wid] = v;
        __syncthreads();
        if (tid < 8) {
            float2 w = wsum[tid];
#pragma unroll
            for (int o = 1; o < 8; o <<= 1) {
                float nx = __shfl_up_sync(0xFFu, w.x, o);
                float ny = __shfl_up_sync(0xFFu, w.y, o);
                if (tid >= o) { w.x += nx; w.y += ny; }
            }
            wsum[tid] = w;
        }
        __syncthreads();
        float2 off = (wid > 0) ? wsum[wid - 1] : make_float2(0.f, 0.f);
        float2 C = make_float2(off.x + v.x, off.y + v.y);
        psum[buf][tid + 1] = C;
        if (tid == 0) psum[buf][0] = make_float2(0.f, 0.f);
        __syncthreads();

        if (is_out) {
            const float2 h2 = psum[buf][tid + RAD + 1];
            const float2 l2 = psum[buf][tid - RAD];
            const float cy  = (float)(min(rr + RAD, HH - 1) - max(rr - RAD, 0) + 1);
            const float inv = 1.0f / (cx * cy);
            const float ma = (h2.x - l2.x) * inv;
            const float mb = (h2.y - l2.y) * inv;
            out[(size_t)img * PLANE + (size_t)rr * WW + c] = ma * iv + mb;
        }

        s.x += aa - sa;
        s.y += ab - sb;
        buf ^= 1;
    }
}

extern "C" void kernel_launch(void* const* d_in, const int* in_sizes, int n_in,
                              void* d_out, int out_size) {
    const float* I = (const float*)d_in[0];
    const float* P = (const float*)d_in[1];
    float* out = (float*)d_out;

    dim3 grid(NBX, HH / VSEG, NIMG);
    gf_k1<<<grid, 256>>>(I, P);
    gf_k2<<<grid, 256>>>(I, out);
}